// round 3
// baseline (speedup 1.0000x reference)
#include <cuda_runtime.h>
#include <cuda_bf16.h>

#define NBINS 256
#define NCH 3
#define NHIST (NBINS * NCH)      // 768
#define BLOCK_THREADS 512
#define NWARPS (BLOCK_THREADS / 32)   // 16 — one shared replica per warp
#define GRID_BLOCKS 296               // 2 CTAs per SM (148 SMs)

// Per-block partial histograms: overwritten (plain STG) every launch,
// so no zeroing kernel is needed and replays stay deterministic.
__device__ unsigned int g_partial[GRID_BLOCKS * NHIST];

__device__ __forceinline__ int bin_of(float x) {
    // TF histogram_fixed_width rule: clip(int(x*256), 0, 255), trunc toward zero
    int b = __float2int_rz(x * 256.0f);
    return max(0, min(255, b));
}

__global__ void __launch_bounds__(BLOCK_THREADS, 2)
hist_kernel(const float4* __restrict__ in4, int n4,
            const float* __restrict__ in, int n_total) {
    __shared__ unsigned int sh[NWARPS][NHIST];   // 48 KB

    // Zero this block's replicas
    for (int i = threadIdx.x; i < NWARPS * NHIST; i += BLOCK_THREADS)
        ((unsigned int*)sh)[i] = 0u;
    __syncthreads();

    // Private per-warp replica: no inter-warp same-address serialization
    unsigned int* h = sh[threadIdx.x >> 5];

    const int stride = gridDim.x * BLOCK_THREADS;
    for (int j = blockIdx.x * BLOCK_THREADS + threadIdx.x; j < n4; j += stride) {
        float4 v = in4[j];
        // base element index = 4*j; 4 == 1 (mod 3) => base channel = j % 3
        int c0 = j % 3;
        int c1 = c0 + 1; if (c1 >= 3) c1 -= 3;
        int c2 = c1 + 1; if (c2 >= 3) c2 -= 3;
        atomicAdd(&h[c0 * NBINS + bin_of(v.x)], 1u);
        atomicAdd(&h[c1 * NBINS + bin_of(v.y)], 1u);
        atomicAdd(&h[c2 * NBINS + bin_of(v.z)], 1u);
        atomicAdd(&h[c0 * NBINS + bin_of(v.w)], 1u);   // 4th wraps to c0
    }

    // Scalar tail (n_total % 4 != 0) — block 0 only (no-op for this shape)
    if (blockIdx.x == 0) {
        for (int i = n4 * 4 + threadIdx.x; i < n_total; i += BLOCK_THREADS) {
            int c = i % 3;
            atomicAdd(&h[c * NBINS + bin_of(in[i])], 1u);
        }
    }

    __syncthreads();

    // Reduce the 16 replicas and publish this block's partial row (coalesced STG)
    for (int i = threadIdx.x; i < NHIST; i += BLOCK_THREADS) {
        unsigned int s = 0u;
        #pragma unroll
        for (int r = 0; r < NWARPS; r++) s += sh[r][i];
        g_partial[blockIdx.x * NHIST + i] = s;
    }
}

// 12 blocks x 64 threads = 768 threads, one bin each; column sums are coalesced.
__global__ void __launch_bounds__(64)
finalize_kernel(float* __restrict__ out, float inv_total) {
    int i = blockIdx.x * 64 + threadIdx.x;   // flat bin id: c*256 + bin
    unsigned int s = 0u;
    int b = 0;
    #pragma unroll 8
    for (; b + 8 <= GRID_BLOCKS; b += 8) {
        s += g_partial[(b + 0) * NHIST + i];
        s += g_partial[(b + 1) * NHIST + i];
        s += g_partial[(b + 2) * NHIST + i];
        s += g_partial[(b + 3) * NHIST + i];
        s += g_partial[(b + 4) * NHIST + i];
        s += g_partial[(b + 5) * NHIST + i];
        s += g_partial[(b + 6) * NHIST + i];
        s += g_partial[(b + 7) * NHIST + i];
    }
    for (; b < GRID_BLOCKS; b++) s += g_partial[b * NHIST + i];

    int c   = i >> 8;          // channel
    int bin = i & (NBINS - 1); // bin
    // reference output is hist.T -> [nbins, 3] row-major
    out[bin * NCH + c] = (float)s * inv_total;
}

extern "C" void kernel_launch(void* const* d_in, const int* in_sizes, int n_in,
                              void* d_out, int out_size) {
    const float* in = (const float*)d_in[0];
    int n = in_sizes[0];                 // 64*512*512*3 = 50,331,648
    int n4 = n / 4;
    float inv_total = 1.0f / (float)(n / 3);   // per-channel pixel count (exact, power of 2)

    hist_kernel<<<GRID_BLOCKS, BLOCK_THREADS>>>((const float4*)in, n4, in, n);
    finalize_kernel<<<NHIST / 64, 64>>>((float*)d_out, inv_total);
}

// round 5
// speedup vs baseline: 1.3082x; 1.3082x over previous
#include <cuda_runtime.h>
#include <cuda_bf16.h>

#define NBINS 256
#define NCH 3
#define NHIST (NBINS * NCH)        // 768
#define BLOCK_THREADS 256
#define NWARPS (BLOCK_THREADS / 32)  // 8 — one shared replica per warp
#define GRID_BLOCKS (148 * 8)        // 1184 blocks, 8 CTAs/SM

// Zero at module load; finalize_kernel re-zeroes after reading, so every
// call (correctness run and each graph replay) starts from zero.
__device__ unsigned int g_counts[NHIST];

__device__ __forceinline__ int bin_of(float x) {
    // TF histogram_fixed_width rule: clip(int(x*256), 0, 255), trunc toward zero
    int b = __float2int_rz(x * 256.0f);
    return max(0, min(255, b));
}

__global__ void __launch_bounds__(BLOCK_THREADS, 8)
hist_kernel(const float4* __restrict__ in4, int n4,
            const float* __restrict__ in, int n_total) {
    __shared__ unsigned int sh[NWARPS][NHIST];   // 24 KB -> 8 CTAs/SM

    // Zero this block's replicas
    for (int i = threadIdx.x; i < NWARPS * NHIST; i += BLOCK_THREADS)
        ((unsigned int*)sh)[i] = 0u;
    __syncthreads();

    // Private per-warp replica: no inter-warp same-address serialization
    unsigned int* h = sh[threadIdx.x >> 5];

    const int stride = gridDim.x * BLOCK_THREADS;
    for (int j = blockIdx.x * BLOCK_THREADS + threadIdx.x; j < n4; j += stride) {
        float4 v = in4[j];
        // base element index = 4*j; 4 == 1 (mod 3) => base channel = j % 3
        int c0 = j % 3;
        int c1 = c0 + 1; if (c1 >= 3) c1 -= 3;
        int c2 = c1 + 1; if (c2 >= 3) c2 -= 3;
        atomicAdd(&h[c0 * NBINS + bin_of(v.x)], 1u);
        atomicAdd(&h[c1 * NBINS + bin_of(v.y)], 1u);
        atomicAdd(&h[c2 * NBINS + bin_of(v.z)], 1u);
        atomicAdd(&h[c0 * NBINS + bin_of(v.w)], 1u);   // 4th wraps to c0
    }

    // Scalar tail (n_total % 4 != 0) — block 0 only (no-op for this shape)
    if (blockIdx.x == 0) {
        for (int i = n4 * 4 + threadIdx.x; i < n_total; i += BLOCK_THREADS) {
            int c = i % 3;
            atomicAdd(&h[c * NBINS + bin_of(in[i])], 1u);
        }
    }

    __syncthreads();

    // Reduce the 8 per-warp replicas and publish (768 global atomics/block)
    for (int i = threadIdx.x; i < NHIST; i += BLOCK_THREADS) {
        unsigned int s = 0u;
        #pragma unroll
        for (int r = 0; r < NWARPS; r++) s += sh[r][i];
        if (s) atomicAdd(&g_counts[i], s);
    }
}

// 768 threads total: read the final counts, write normalized output,
// then reset the counters for the next replay.
__global__ void __launch_bounds__(256)
finalize_kernel(float* __restrict__ out, float inv_total) {
    int i = blockIdx.x * 256 + threadIdx.x;   // flat bin id: c*256 + bin
    if (i < NHIST) {
        unsigned int s = g_counts[i];
        g_counts[i] = 0u;                     // restore invariant for next call
        int c   = i >> 8;                     // channel
        int bin = i & (NBINS - 1);            // bin
        // reference output is hist.T -> [nbins, 3] row-major
        out[bin * NCH + c] = (float)s * inv_total;
    }
}

extern "C" void kernel_launch(void* const* d_in, const int* in_sizes, int n_in,
                              void* d_out, int out_size) {
    const float* in = (const float*)d_in[0];
    int n = in_sizes[0];                 // 64*512*512*3 = 50,331,648
    int n4 = n / 4;
    float inv_total = 1.0f / (float)(n / 3);   // per-channel pixel count (exact)

    hist_kernel<<<GRID_BLOCKS, BLOCK_THREADS>>>((const float4*)in, n4, in, n);
    finalize_kernel<<<(NHIST + 255) / 256, 256>>>((float*)d_out, inv_total);
}